// round 9
// baseline (speedup 1.0000x reference)
#include <cuda_runtime.h>
#include <cstdint>

// Problem constants (B=16, C=64, H=W=128, heads=4)
#define NBH    64        // B * heads
#define CPH    16        // channels per head
#define HW     16384     // H * W
#define SPLITS 16
#define KSPL   1024      // HW / SPLITS
#define TS     32        // k-floats per tile (one 128B line per row)
#define NT     (KSPL / TS)        // 32 tiles
#define BUF    1024      // floats per stage: x 16x32 + y 16x32
#define NBUF   4

typedef unsigned long long u64;

// Scratch (no cudaMalloc allowed)
__device__ float g_scr[SPLITS][NBH][288];   // per-(split,bh): 256 gram + 16 nx + 16 ny
__device__ float g_M1[NBH][256];            // t1 * attn1[c][d]
__device__ float g_M2[NBH][256];            // t2 * attn2[c][d]

__device__ __forceinline__ void cp16(uint32_t saddr, const void* gaddr) {
    asm volatile("cp.async.cg.shared.global [%0], [%1], 16;\n" :: "r"(saddr), "l"(gaddr));
}
__device__ __forceinline__ void cp_commit() { asm volatile("cp.async.commit_group;\n"); }
__device__ __forceinline__ void cp_wait1()  { asm volatile("cp.async.wait_group 1;\n" ::: "memory"); }
__device__ __forceinline__ void cp_wait0()  { asm volatile("cp.async.wait_group 0;\n" ::: "memory"); }

// Packed f32x2 FMA (sm_103a FFMA2 — ptxas never auto-fuses)
__device__ __forceinline__ u64 fma2(u64 a, u64 b, u64 c) {
    u64 d;
    asm("fma.rn.f32x2 %0, %1, %2, %3;" : "=l"(d) : "l"(a), "l"(b), "l"(c));
    return d;
}
__device__ __forceinline__ u64 pk2(float lo, float hi) {
    u64 r;
    asm("mov.b64 %0, {%1, %2};" : "=l"(r) : "f"(lo), "f"(hi));
    return r;
}
__device__ __forceinline__ float hsum2(u64 v) {
    float lo, hi;
    asm("mov.b64 {%0, %1}, %2;" : "=f"(lo), "=f"(hi) : "l"(v));
    return lo + hi;
}

struct U2 { u64 a, b; };
__device__ __forceinline__ U2 ldcs_u2(const void* p) {
    U2 r;
    asm("ld.global.cs.v2.u64 {%0, %1}, [%2];" : "=l"(r.a), "=l"(r.b) : "l"(p));
    return r;
}
__device__ __forceinline__ void stcs_u2(void* p, U2 v) {
    asm volatile("st.global.cs.v2.b64 [%0], {%1, %2};" :: "l"(p), "l"(v.a), "l"(v.b) : "memory");
}

// ---------------------------------------------------------------------------
// Kernel 1: per (split, bh) partial Gram + row sum-of-squares.
// R7 structure (128-thr CTAs, 4-warp barrier domain, cp.async 4-buffer ring,
// depth 2) with packed f32x2 accumulation: 32 FFMA2 replace 64 FFMA per tile.
// Warp w: x rows 4w..4w+3 (broadcast LDS); y rows grouped-interleaved so each
// y LDS.128 is 512B contiguous (conflict-free).
// ---------------------------------------------------------------------------
__global__ __launch_bounds__(128, 6) void k_gram(const float* __restrict__ x,
                                                 const float* __restrict__ y) {
    const int s  = blockIdx.x;
    const int bh = blockIdx.y;
    const int t  = threadIdx.x;
    const int g  = t >> 3;         // 16 quadrants
    const int kp = t & 7;          // float4 k-phase
    const int dg = g & 3;          // d-group (lane>>3 within warp)
    const int w  = g >> 2;         // warp id
    const int c0 = w * 4;
    const int d0 = dg * 4;

    __shared__ float sbuf[NBUF * BUF];

    // Staging: thread t copies x[srow, sq] and y[srow, sq] (sq = 16B chunk).
    const int srow = g;
    const int sq   = kp;
    const uint32_t sb = (uint32_t)__cvta_generic_to_shared(sbuf);
    const uint32_t offX = (uint32_t)(srow * 8 + sq) * 16u;
    const uint32_t offY = 2048u + (uint32_t)((((srow & 3) * 4) + (srow >> 2)) * 8 + sq) * 16u;
    const float* gx = x + (size_t)bh * CPH * HW + srow * HW + s * KSPL + sq * 4;
    const float* gy = y + (size_t)bh * CPH * HW + srow * HW + s * KSPL + sq * 4;

    u64 acc2[4][4];
#pragma unroll
    for (int i = 0; i < 4; i++)
#pragma unroll
        for (int j = 0; j < 4; j++) acc2[i][j] = 0ull;
    u64 nx2[4], ny2[4];
#pragma unroll
    for (int i = 0; i < 4; i++) { nx2[i] = 0ull; ny2[i] = 0ull; }

    // Prologue: tiles 0 and 1 in flight
#pragma unroll
    for (int p = 0; p < 2; p++) {
        const uint32_t base = sb + (uint32_t)(p * BUF * 4);
        cp16(base + offX, gx + p * TS);
        cp16(base + offY, gy + p * TS);
        cp_commit();
    }

    for (int tile = 0; tile < NT; ++tile) {
        if (tile == NT - 1) cp_wait0(); else cp_wait1();
        __syncthreads();
        if (tile + 2 < NT) {
            const uint32_t base = sb + (uint32_t)(((tile + 2) & (NBUF - 1)) * BUF * 4);
            cp16(base + offX, gx + (tile + 2) * TS);
            cp16(base + offY, gy + (tile + 2) * TS);
            cp_commit();
        }

        const float* xs = sbuf + (tile & (NBUF - 1)) * BUF;
        const float* ys = xs + 512;

        ulonglong2 xv[4], yv[4];   // each = 4 floats = 2 packed k-pairs
#pragma unroll
        for (int i = 0; i < 4; i++)
            xv[i] = *reinterpret_cast<const ulonglong2*>(xs + (c0 + i) * TS + kp * 4);
#pragma unroll
        for (int j = 0; j < 4; j++)
            yv[j] = *reinterpret_cast<const ulonglong2*>(ys + ((j * 4 + dg) * 8 + kp) * 4);

#pragma unroll
        for (int i = 0; i < 4; i++)
#pragma unroll
            for (int j = 0; j < 4; j++) {
                u64 a = acc2[i][j];
                a = fma2(xv[i].x, yv[j].x, a);
                a = fma2(xv[i].y, yv[j].y, a);
                acc2[i][j] = a;
            }
        if (dg == 0) {     // x rows unique per warp; count once
#pragma unroll
            for (int i = 0; i < 4; i++) {
                u64 a = nx2[i];
                a = fma2(xv[i].x, xv[i].x, a);
                a = fma2(xv[i].y, xv[i].y, a);
                nx2[i] = a;
            }
        }
        if (w == 0) {      // y rows shared by all warps; warp 0 counts
#pragma unroll
            for (int j = 0; j < 4; j++) {
                u64 a = ny2[j];
                a = fma2(yv[j].x, yv[j].x, a);
                a = fma2(yv[j].y, yv[j].y, a);
                ny2[j] = a;
            }
        }
    }

    // Unpack, then reduce over the 8 kp phases (lane bits 0..2).
    float acc[4][4], nxa[4], nya[4];
#pragma unroll
    for (int i = 0; i < 4; i++) {
#pragma unroll
        for (int j = 0; j < 4; j++) acc[i][j] = hsum2(acc2[i][j]);
        nxa[i] = hsum2(nx2[i]);
        nya[i] = hsum2(ny2[i]);
    }
#pragma unroll
    for (int m = 1; m <= 4; m <<= 1) {
#pragma unroll
        for (int i = 0; i < 4; i++)
#pragma unroll
            for (int j = 0; j < 4; j++)
                acc[i][j] += __shfl_xor_sync(0xffffffffu, acc[i][j], m);
#pragma unroll
        for (int i = 0; i < 4; i++) {
            nxa[i] += __shfl_xor_sync(0xffffffffu, nxa[i], m);
            nya[i] += __shfl_xor_sync(0xffffffffu, nya[i], m);
        }
    }

    if (kp == 0) {
#pragma unroll
        for (int i = 0; i < 4; i++)
#pragma unroll
            for (int j = 0; j < 4; j++)
                g_scr[s][bh][(c0 + i) * 16 + (d0 + j)] = acc[i][j];
        if (dg == 0) {
#pragma unroll
            for (int i = 0; i < 4; i++) g_scr[s][bh][256 + c0 + i] = nxa[i];
        }
        if (w == 0) {
#pragma unroll
            for (int j = 0; j < 4; j++) g_scr[s][bh][272 + d0 + j] = nya[j];
        }
    }
}

// ---------------------------------------------------------------------------
// Kernel 2: energy, dual softmax, temperature pre-scale
// ---------------------------------------------------------------------------
__global__ __launch_bounds__(256) void k_attn(const float* __restrict__ t1p,
                                              const float* __restrict__ t2p) {
    const int bh = blockIdx.x;
    const int t  = threadIdx.x;
    __shared__ float sE[256];
    __shared__ float sNx[16];
    __shared__ float sNy[16];

    float gsum = 0.f;
#pragma unroll
    for (int s = 0; s < SPLITS; s++) gsum += g_scr[s][bh][t];
    if (t < 16) {
        float nx = 0.f;
#pragma unroll
        for (int s = 0; s < SPLITS; s++) nx += g_scr[s][bh][256 + t];
        sNx[t] = fmaxf(sqrtf(nx), 1e-12f);
    } else if (t < 32) {
        const int d = t - 16;
        float ny = 0.f;
#pragma unroll
        for (int s = 0; s < SPLITS; s++) ny += g_scr[s][bh][272 + d];
        sNy[d] = fmaxf(sqrtf(ny), 1e-12f);
    }
    __syncthreads();

    const int c = t >> 4, d = t & 15;
    const float e = gsum / (sNx[c] * sNy[d]);
    sE[t] = e;

    // attn1: softmax over d (lane low 4 bits)
    float m = e;
#pragma unroll
    for (int msk = 1; msk <= 8; msk <<= 1)
        m = fmaxf(m, __shfl_xor_sync(0xffffffffu, m, msk));
    float p = __expf(e - m);
    float Z = p;
#pragma unroll
    for (int msk = 1; msk <= 8; msk <<= 1)
        Z += __shfl_xor_sync(0xffffffffu, Z, msk);
    g_M1[bh][t] = t1p[0] * (p / Z);

    __syncthreads();
    // attn2[c][d] = softmax over column of energy
    const float f = sE[d * 16 + c];
    float m2 = f;
#pragma unroll
    for (int msk = 1; msk <= 8; msk <<= 1)
        m2 = fmaxf(m2, __shfl_xor_sync(0xffffffffu, m2, msk));
    float p2 = __expf(f - m2);
    float Z2 = p2;
#pragma unroll
    for (int msk = 1; msk <= 8; msk <<= 1)
        Z2 += __shfl_xor_sync(0xffffffffu, Z2, msk);
    g_M2[bh][t] = t2p[0] * (p2 / Z2);
}

// ---------------------------------------------------------------------------
// Kernel 3: apply attention + residual + concat.
// Duplicate-packed u64 matrices in smem (LDS.64 broadcast, no in-loop MOVs);
// fma.rn.f32x2; streaming ld/st hints.
// out[:, 0:64]  = t2 * x_att + y
// out[:, 64:128]= t1 * y_att + x
// ---------------------------------------------------------------------------
__global__ __launch_bounds__(128) void k_apply(const float* __restrict__ x,
                                               const float* __restrict__ y,
                                               float* __restrict__ out) {
    const int bh = blockIdx.y;
    const int kc = blockIdx.x;
    const int t  = threadIdx.x;
    __shared__ u64 sD1[256];   // pk2(m1, m1)
    __shared__ u64 sD2[256];   // pk2(m2, m2)
    {
        float a0 = g_M1[bh][t],       b0 = g_M2[bh][t];
        float a1 = g_M1[bh][t + 128], b1 = g_M2[bh][t + 128];
        sD1[t]       = pk2(a0, a0);
        sD2[t]       = pk2(b0, b0);
        sD1[t + 128] = pk2(a1, a1);
        sD2[t + 128] = pk2(b1, b1);
    }
    __syncthreads();

    const int b = bh >> 2, h = bh & 3;
    const int k4 = kc * 128 + t;                 // 16-byte column index
    const char* xb = reinterpret_cast<const char*>(x + (size_t)bh * CPH * HW);
    const char* yb = reinterpret_cast<const char*>(y + (size_t)bh * CPH * HW);

    U2 xv[16], yv[16];
#pragma unroll
    for (int c = 0; c < 16; c++) {
        xv[c] = ldcs_u2(xb + ((size_t)c * (HW / 4) + k4) * 16);
        yv[c] = ldcs_u2(yb + ((size_t)c * (HW / 4) + k4) * 16);
    }

    char* ob = reinterpret_cast<char*>(out + (size_t)b * 128 * HW);
#pragma unroll
    for (int d = 0; d < 16; d++) {
        U2 ay, ax;
        ay.a = xv[d].a; ay.b = xv[d].b;   // y_ = t1*y_att + x
        ax.a = yv[d].a; ax.b = yv[d].b;   // x_ = t2*x_att + y
#pragma unroll
        for (int c = 0; c < 16; c++) {
            const u64 m1d = sD1[c * 16 + d];
            const u64 m2d = sD2[c * 16 + d];
            ay.a = fma2(m1d, yv[c].a, ay.a);
            ay.b = fma2(m1d, yv[c].b, ay.b);
            ax.a = fma2(m2d, xv[c].a, ax.a);
            ax.b = fma2(m2d, xv[c].b, ax.b);
        }
        stcs_u2(ob + ((size_t)(h * 16 + d) * (HW / 4) + k4) * 16, ax);       // ch 0..63
        stcs_u2(ob + ((size_t)(64 + h * 16 + d) * (HW / 4) + k4) * 16, ay);  // ch 64..127
    }
}

// ---------------------------------------------------------------------------
extern "C" void kernel_launch(void* const* d_in, const int* in_sizes, int n_in,
                              void* d_out, int out_size) {
    const float* x  = (const float*)d_in[0];
    const float* y  = (const float*)d_in[1];
    const float* t1 = (const float*)d_in[2];
    const float* t2 = (const float*)d_in[3];
    float* out = (float*)d_out;

    k_gram<<<dim3(SPLITS, NBH), 128>>>(x, y);
    k_attn<<<NBH, 256>>>(t1, t2);
    k_apply<<<dim3(HW / 4 / 128, NBH), 128>>>(x, y, out);
}

// round 10
// speedup vs baseline: 1.1577x; 1.1577x over previous
#include <cuda_runtime.h>
#include <cstdint>

// Problem constants (B=16, C=64, H=W=128, heads=4)
#define NBH    64        // B * heads
#define CPH    16        // channels per head
#define HW     16384     // H * W
#define SPLITS 16
#define KSPL   1024      // HW / SPLITS
#define TS     32        // k-floats per tile (one 128B line per row)
#define NT     (KSPL / TS)        // 32 tiles
#define BUF    1024      // floats per stage: x 16x32 + y 16x32
#define NBUF   4

typedef unsigned long long u64;

// Scratch (no cudaMalloc allowed)
__device__ float g_scr[SPLITS][NBH][288];   // per-(split,bh): 256 gram + 16 nx + 16 ny
__device__ float g_M1[NBH][256];            // t1 * attn1[c][d]
__device__ float g_M2[NBH][256];            // t2 * attn2[c][d]

__device__ __forceinline__ void cp16(uint32_t saddr, const void* gaddr) {
    asm volatile("cp.async.cg.shared.global [%0], [%1], 16;\n" :: "r"(saddr), "l"(gaddr));
}
__device__ __forceinline__ void cp_commit() { asm volatile("cp.async.commit_group;\n"); }
__device__ __forceinline__ void cp_wait2()  { asm volatile("cp.async.wait_group 2;\n" ::: "memory"); }
__device__ __forceinline__ void cp_wait1()  { asm volatile("cp.async.wait_group 1;\n" ::: "memory"); }
__device__ __forceinline__ void cp_wait0()  { asm volatile("cp.async.wait_group 0;\n" ::: "memory"); }

// Packed f32x2 FMA (sm_103a FFMA2) — used ONLY in k_apply (occupancy-safe there)
__device__ __forceinline__ u64 fma2(u64 a, u64 b, u64 c) {
    u64 d;
    asm("fma.rn.f32x2 %0, %1, %2, %3;" : "=l"(d) : "l"(a), "l"(b), "l"(c));
    return d;
}
__device__ __forceinline__ u64 pk2(float lo, float hi) {
    u64 r;
    asm("mov.b64 %0, {%1, %2};" : "=l"(r) : "f"(lo), "f"(hi));
    return r;
}

struct U2 { u64 a, b; };
__device__ __forceinline__ U2 ldcs_u2(const void* p) {
    U2 r;
    asm("ld.global.cs.v2.u64 {%0, %1}, [%2];" : "=l"(r.a), "=l"(r.b) : "l"(p));
    return r;
}
__device__ __forceinline__ void stcs_u2(void* p, U2 v) {
    asm volatile("st.global.cs.v2.b64 [%0], {%1, %2};" :: "l"(p), "l"(v.a), "l"(v.b) : "memory");
}

// ---------------------------------------------------------------------------
// Kernel 1: per (split, bh) partial Gram + row sum-of-squares.
// 128-thread CTAs (4-warp barrier domain), 8 CTAs/SM -> independent pipelines.
// cp.async 4-buffer ring, DEPTH 3, 32-float k-tiles. Scalar FMA (FFMA2 banned
// here: costs regs -> occupancy, measured 3x).
// Warp w: x rows 4w..4w+3 (broadcast LDS); y rows grouped-interleaved so each
// y LDS.128 is 512B contiguous (conflict-free).
// ---------------------------------------------------------------------------
__global__ __launch_bounds__(128, 8) void k_gram(const float* __restrict__ x,
                                                 const float* __restrict__ y) {
    const int s  = blockIdx.x;
    const int bh = blockIdx.y;
    const int t  = threadIdx.x;
    const int g  = t >> 3;         // 16 quadrants
    const int kp = t & 7;          // float4 k-phase
    const int dg = g & 3;          // d-group (lane>>3 within warp)
    const int w  = g >> 2;         // warp id
    const int c0 = w * 4;
    const int d0 = dg * 4;

    __shared__ float sbuf[NBUF * BUF];

    // Staging: thread t copies x[srow, sq] and y[srow, sq] (sq = 16B chunk).
    const int srow = g;
    const int sq   = kp;
    const uint32_t sb = (uint32_t)__cvta_generic_to_shared(sbuf);
    const uint32_t offX = (uint32_t)(srow * 8 + sq) * 16u;
    const uint32_t offY = 2048u + (uint32_t)((((srow & 3) * 4) + (srow >> 2)) * 8 + sq) * 16u;
    const float* gx = x + (size_t)bh * CPH * HW + srow * HW + s * KSPL + sq * 4;
    const float* gy = y + (size_t)bh * CPH * HW + srow * HW + s * KSPL + sq * 4;

    float acc[4][4];
#pragma unroll
    for (int i = 0; i < 4; i++)
#pragma unroll
        for (int j = 0; j < 4; j++) acc[i][j] = 0.f;
    float nxa[4], nya[4];
#pragma unroll
    for (int i = 0; i < 4; i++) { nxa[i] = 0.f; nya[i] = 0.f; }

    // Prologue: tiles 0, 1, 2 in flight (depth 3)
#pragma unroll
    for (int p = 0; p < 3; p++) {
        const uint32_t base = sb + (uint32_t)(p * BUF * 4);
        cp16(base + offX, gx + p * TS);
        cp16(base + offY, gy + p * TS);
        cp_commit();
    }

    for (int tile = 0; tile < NT; ++tile) {
        if (tile < NT - 2)       cp_wait2();
        else if (tile == NT - 2) cp_wait1();
        else                     cp_wait0();
        __syncthreads();
        if (tile + 3 < NT) {
            const uint32_t base = sb + (uint32_t)(((tile + 3) & (NBUF - 1)) * BUF * 4);
            cp16(base + offX, gx + (tile + 3) * TS);
            cp16(base + offY, gy + (tile + 3) * TS);
            cp_commit();
        }

        const float* xs = sbuf + (tile & (NBUF - 1)) * BUF;
        const float* ys = xs + 512;

        float4 xv[4], yv[4];
#pragma unroll
        for (int i = 0; i < 4; i++)
            xv[i] = *reinterpret_cast<const float4*>(xs + (c0 + i) * TS + kp * 4);
#pragma unroll
        for (int j = 0; j < 4; j++)
            yv[j] = *reinterpret_cast<const float4*>(ys + ((j * 4 + dg) * 8 + kp) * 4);

#pragma unroll
        for (int i = 0; i < 4; i++)
#pragma unroll
            for (int j = 0; j < 4; j++) {
                float a = acc[i][j];
                a = fmaf(xv[i].x, yv[j].x, a);
                a = fmaf(xv[i].y, yv[j].y, a);
                a = fmaf(xv[i].z, yv[j].z, a);
                a = fmaf(xv[i].w, yv[j].w, a);
                acc[i][j] = a;
            }
        if (dg == 0) {     // x rows unique per warp; count once
#pragma unroll
            for (int i = 0; i < 4; i++) {
                float a = nxa[i];
                a = fmaf(xv[i].x, xv[i].x, a);
                a = fmaf(xv[i].y, xv[i].y, a);
                a = fmaf(xv[i].z, xv[i].z, a);
                a = fmaf(xv[i].w, xv[i].w, a);
                nxa[i] = a;
            }
        }
        if (w == 0) {      // y rows shared by all warps; warp 0 counts
#pragma unroll
            for (int j = 0; j < 4; j++) {
                float a = nya[j];
                a = fmaf(yv[j].x, yv[j].x, a);
                a = fmaf(yv[j].y, yv[j].y, a);
                a = fmaf(yv[j].z, yv[j].z, a);
                a = fmaf(yv[j].w, yv[j].w, a);
                nya[j] = a;
            }
        }
    }

    // Reduce over the 8 kp phases (lane bits 0..2); each (g,kp) unique -> done.
#pragma unroll
    for (int m = 1; m <= 4; m <<= 1) {
#pragma unroll
        for (int i = 0; i < 4; i++)
#pragma unroll
            for (int j = 0; j < 4; j++)
                acc[i][j] += __shfl_xor_sync(0xffffffffu, acc[i][j], m);
#pragma unroll
        for (int i = 0; i < 4; i++) {
            nxa[i] += __shfl_xor_sync(0xffffffffu, nxa[i], m);
            nya[i] += __shfl_xor_sync(0xffffffffu, nya[i], m);
        }
    }

    if (kp == 0) {
#pragma unroll
        for (int i = 0; i < 4; i++)
#pragma unroll
            for (int j = 0; j < 4; j++)
                g_scr[s][bh][(c0 + i) * 16 + (d0 + j)] = acc[i][j];
        if (dg == 0) {
#pragma unroll
            for (int i = 0; i < 4; i++) g_scr[s][bh][256 + c0 + i] = nxa[i];
        }
        if (w == 0) {
#pragma unroll
            for (int j = 0; j < 4; j++) g_scr[s][bh][272 + d0 + j] = nya[j];
        }
    }
}

// ---------------------------------------------------------------------------
// Kernel 2: energy, dual softmax, temperature pre-scale
// ---------------------------------------------------------------------------
__global__ __launch_bounds__(256) void k_attn(const float* __restrict__ t1p,
                                              const float* __restrict__ t2p) {
    const int bh = blockIdx.x;
    const int t  = threadIdx.x;
    __shared__ float sE[256];
    __shared__ float sNx[16];
    __shared__ float sNy[16];

    float gsum = 0.f;
#pragma unroll
    for (int s = 0; s < SPLITS; s++) gsum += g_scr[s][bh][t];
    if (t < 16) {
        float nx = 0.f;
#pragma unroll
        for (int s = 0; s < SPLITS; s++) nx += g_scr[s][bh][256 + t];
        sNx[t] = fmaxf(sqrtf(nx), 1e-12f);
    } else if (t < 32) {
        const int d = t - 16;
        float ny = 0.f;
#pragma unroll
        for (int s = 0; s < SPLITS; s++) ny += g_scr[s][bh][272 + d];
        sNy[d] = fmaxf(sqrtf(ny), 1e-12f);
    }
    __syncthreads();

    const int c = t >> 4, d = t & 15;
    const float e = gsum / (sNx[c] * sNy[d]);
    sE[t] = e;

    // attn1: softmax over d (lane low 4 bits)
    float m = e;
#pragma unroll
    for (int msk = 1; msk <= 8; msk <<= 1)
        m = fmaxf(m, __shfl_xor_sync(0xffffffffu, m, msk));
    float p = __expf(e - m);
    float Z = p;
#pragma unroll
    for (int msk = 1; msk <= 8; msk <<= 1)
        Z += __shfl_xor_sync(0xffffffffu, Z, msk);
    g_M1[bh][t] = t1p[0] * (p / Z);

    __syncthreads();
    // attn2[c][d] = softmax over column of energy
    const float f = sE[d * 16 + c];
    float m2 = f;
#pragma unroll
    for (int msk = 1; msk <= 8; msk <<= 1)
        m2 = fmaxf(m2, __shfl_xor_sync(0xffffffffu, m2, msk));
    float p2 = __expf(f - m2);
    float Z2 = p2;
#pragma unroll
    for (int msk = 1; msk <= 8; msk <<= 1)
        Z2 += __shfl_xor_sync(0xffffffffu, Z2, msk);
    g_M2[bh][t] = t2p[0] * (p2 / Z2);
}

// ---------------------------------------------------------------------------
// Kernel 3: apply attention + residual + concat.
// Duplicate-packed u64 matrices in smem (LDS.64 broadcast, no in-loop MOVs);
// fma.rn.f32x2; streaming ld/st hints.
// out[:, 0:64]  = t2 * x_att + y
// out[:, 64:128]= t1 * y_att + x
// ---------------------------------------------------------------------------
__global__ __launch_bounds__(128) void k_apply(const float* __restrict__ x,
                                               const float* __restrict__ y,
                                               float* __restrict__ out) {
    const int bh = blockIdx.y;
    const int kc = blockIdx.x;
    const int t  = threadIdx.x;
    __shared__ u64 sD1[256];   // pk2(m1, m1)
    __shared__ u64 sD2[256];   // pk2(m2, m2)
    {
        float a0 = g_M1[bh][t],       b0 = g_M2[bh][t];
        float a1 = g_M1[bh][t + 128], b1 = g_M2[bh][t + 128];
        sD1[t]       = pk2(a0, a0);
        sD2[t]       = pk2(b0, b0);
        sD1[t + 128] = pk2(a1, a1);
        sD2[t + 128] = pk2(b1, b1);
    }
    __syncthreads();

    const int b = bh >> 2, h = bh & 3;
    const int k4 = kc * 128 + t;                 // 16-byte column index
    const char* xb = reinterpret_cast<const char*>(x + (size_t)bh * CPH * HW);
    const char* yb = reinterpret_cast<const char*>(y + (size_t)bh * CPH * HW);

    U2 xv[16], yv[16];
#pragma unroll
    for (int c = 0; c < 16; c++) {
        xv[c] = ldcs_u2(xb + ((size_t)c * (HW / 4) + k4) * 16);
        yv[c] = ldcs_u2(yb + ((size_t)c * (HW / 4) + k4) * 16);
    }

    char* ob = reinterpret_cast<char*>(out + (size_t)b * 128 * HW);
#pragma unroll
    for (int d = 0; d < 16; d++) {
        U2 ay, ax;
        ay.a = xv[d].a; ay.b = xv[d].b;   // y_ = t1*y_att + x
        ax.a = yv[d].a; ax.b = yv[d].b;   // x_ = t2*x_att + y
#pragma unroll
        for (int c = 0; c < 16; c++) {
            const u64 m1d = sD1[c * 16 + d];
            const u64 m2d = sD2[c * 16 + d];
            ay.a = fma2(m1d, yv[c].a, ay.a);
            ay.b = fma2(m1d, yv[c].b, ay.b);
            ax.a = fma2(m2d, xv[c].a, ax.a);
            ax.b = fma2(m2d, xv[c].b, ax.b);
        }
        stcs_u2(ob + ((size_t)(h * 16 + d) * (HW / 4) + k4) * 16, ax);       // ch 0..63
        stcs_u2(ob + ((size_t)(64 + h * 16 + d) * (HW / 4) + k4) * 16, ay);  // ch 64..127
    }
}

// ---------------------------------------------------------------------------
extern "C" void kernel_launch(void* const* d_in, const int* in_sizes, int n_in,
                              void* d_out, int out_size) {
    const float* x  = (const float*)d_in[0];
    const float* y  = (const float*)d_in[1];
    const float* t1 = (const float*)d_in[2];
    const float* t2 = (const float*)d_in[3];
    float* out = (float*)d_out;

    k_gram<<<dim3(SPLITS, NBH), 128>>>(x, y);
    k_attn<<<NBH, 256>>>(t1, t2);
    k_apply<<<dim3(HW / 4 / 128, NBH), 128>>>(x, y, out);
}

// round 11
// speedup vs baseline: 1.1612x; 1.0030x over previous
#include <cuda_runtime.h>
#include <cstdint>

// Problem constants (B=16, C=64, H=W=128, heads=4)
#define NBH    64        // B * heads
#define CPH    16        // channels per head
#define HW     16384     // H * W
#define SPLITS 16
#define KSPL   1024      // HW / SPLITS
#define TS     32        // k-floats per tile (one 128B line per row)
#define NT     (KSPL / TS)        // 32 tiles
#define BUF    1024      // floats per stage: x 16x32 + y 16x32
#define NBUF   4

typedef unsigned long long u64;

// Scratch (no cudaMalloc allowed)
__device__ float g_scr[SPLITS][NBH][288];   // per-(split,bh): 256 gram + 16 nx + 16 ny
__device__ float g_M1[NBH][256];            // t1 * attn1[c][d]
__device__ float g_M2[NBH][256];            // t2 * attn2[c][d]

__device__ __forceinline__ void cp16(uint32_t saddr, const void* gaddr) {
    asm volatile("cp.async.cg.shared.global [%0], [%1], 16;\n" :: "r"(saddr), "l"(gaddr));
}
__device__ __forceinline__ void cp_commit() { asm volatile("cp.async.commit_group;\n"); }
__device__ __forceinline__ void cp_wait2()  { asm volatile("cp.async.wait_group 2;\n" ::: "memory"); }
__device__ __forceinline__ void cp_wait1()  { asm volatile("cp.async.wait_group 1;\n" ::: "memory"); }
__device__ __forceinline__ void cp_wait0()  { asm volatile("cp.async.wait_group 0;\n" ::: "memory"); }

// Packed f32x2 FMA (sm_103a FFMA2) — used ONLY in k_apply (occupancy-safe there)
__device__ __forceinline__ u64 fma2(u64 a, u64 b, u64 c) {
    u64 d;
    asm("fma.rn.f32x2 %0, %1, %2, %3;" : "=l"(d) : "l"(a), "l"(b), "l"(c));
    return d;
}
__device__ __forceinline__ u64 pk2(float lo, float hi) {
    u64 r;
    asm("mov.b64 %0, {%1, %2};" : "=l"(r) : "f"(lo), "f"(hi));
    return r;
}

struct U2 { u64 a, b; };
__device__ __forceinline__ U2 ldcs_u2(const void* p) {
    U2 r;
    asm("ld.global.cs.v2.u64 {%0, %1}, [%2];" : "=l"(r.a), "=l"(r.b) : "l"(p));
    return r;
}
__device__ __forceinline__ void stcs_u2(void* p, U2 v) {
    asm volatile("st.global.cs.v2.b64 [%0], {%1, %2};" :: "l"(p), "l"(v.a), "l"(v.b) : "memory");
}

// ---------------------------------------------------------------------------
// Kernel 1: per (split, bh) partial Gram + row sum-of-squares.
// 128-thread CTAs (4-warp barrier domain), 8 CTAs/SM -> independent pipelines.
// cp.async 4-buffer ring, depth 3, 32-float k-tiles. Scalar FMA (FFMA2 banned
// here: costs regs -> occupancy, measured 3x).
// ---------------------------------------------------------------------------
__global__ __launch_bounds__(128, 8) void k_gram(const float* __restrict__ x,
                                                 const float* __restrict__ y) {
    const int s  = blockIdx.x;
    const int bh = blockIdx.y;
    const int t  = threadIdx.x;
    const int g  = t >> 3;         // 16 quadrants
    const int kp = t & 7;          // float4 k-phase
    const int dg = g & 3;          // d-group (lane>>3 within warp)
    const int w  = g >> 2;         // warp id
    const int c0 = w * 4;
    const int d0 = dg * 4;

    __shared__ float sbuf[NBUF * BUF];

    // Staging: thread t copies x[srow, sq] and y[srow, sq] (sq = 16B chunk).
    const int srow = g;
    const int sq   = kp;
    const uint32_t sb = (uint32_t)__cvta_generic_to_shared(sbuf);
    const uint32_t offX = (uint32_t)(srow * 8 + sq) * 16u;
    const uint32_t offY = 2048u + (uint32_t)((((srow & 3) * 4) + (srow >> 2)) * 8 + sq) * 16u;
    const float* gx = x + (size_t)bh * CPH * HW + srow * HW + s * KSPL + sq * 4;
    const float* gy = y + (size_t)bh * CPH * HW + srow * HW + s * KSPL + sq * 4;

    float acc[4][4];
#pragma unroll
    for (int i = 0; i < 4; i++)
#pragma unroll
        for (int j = 0; j < 4; j++) acc[i][j] = 0.f;
    float nxa[4], nya[4];
#pragma unroll
    for (int i = 0; i < 4; i++) { nxa[i] = 0.f; nya[i] = 0.f; }

    // Prologue: tiles 0, 1, 2 in flight (depth 3)
#pragma unroll
    for (int p = 0; p < 3; p++) {
        const uint32_t base = sb + (uint32_t)(p * BUF * 4);
        cp16(base + offX, gx + p * TS);
        cp16(base + offY, gy + p * TS);
        cp_commit();
    }

    for (int tile = 0; tile < NT; ++tile) {
        if (tile < NT - 2)       cp_wait2();
        else if (tile == NT - 2) cp_wait1();
        else                     cp_wait0();
        __syncthreads();
        if (tile + 3 < NT) {
            const uint32_t base = sb + (uint32_t)(((tile + 3) & (NBUF - 1)) * BUF * 4);
            cp16(base + offX, gx + (tile + 3) * TS);
            cp16(base + offY, gy + (tile + 3) * TS);
            cp_commit();
        }

        const float* xs = sbuf + (tile & (NBUF - 1)) * BUF;
        const float* ys = xs + 512;

        float4 xv[4], yv[4];
#pragma unroll
        for (int i = 0; i < 4; i++)
            xv[i] = *reinterpret_cast<const float4*>(xs + (c0 + i) * TS + kp * 4);
#pragma unroll
        for (int j = 0; j < 4; j++)
            yv[j] = *reinterpret_cast<const float4*>(ys + ((j * 4 + dg) * 8 + kp) * 4);

#pragma unroll
        for (int i = 0; i < 4; i++)
#pragma unroll
            for (int j = 0; j < 4; j++) {
                float a = acc[i][j];
                a = fmaf(xv[i].x, yv[j].x, a);
                a = fmaf(xv[i].y, yv[j].y, a);
                a = fmaf(xv[i].z, yv[j].z, a);
                a = fmaf(xv[i].w, yv[j].w, a);
                acc[i][j] = a;
            }
        if (dg == 0) {     // x rows unique per warp; count once
#pragma unroll
            for (int i = 0; i < 4; i++) {
                float a = nxa[i];
                a = fmaf(xv[i].x, xv[i].x, a);
                a = fmaf(xv[i].y, xv[i].y, a);
                a = fmaf(xv[i].z, xv[i].z, a);
                a = fmaf(xv[i].w, xv[i].w, a);
                nxa[i] = a;
            }
        }
        if (w == 0) {      // y rows shared by all warps; warp 0 counts
#pragma unroll
            for (int j = 0; j < 4; j++) {
                float a = nya[j];
                a = fmaf(yv[j].x, yv[j].x, a);
                a = fmaf(yv[j].y, yv[j].y, a);
                a = fmaf(yv[j].z, yv[j].z, a);
                a = fmaf(yv[j].w, yv[j].w, a);
                nya[j] = a;
            }
        }
    }

    // Reduce over the 8 kp phases (lane bits 0..2); each (g,kp) unique -> done.
#pragma unroll
    for (int m = 1; m <= 4; m <<= 1) {
#pragma unroll
        for (int i = 0; i < 4; i++)
#pragma unroll
            for (int j = 0; j < 4; j++)
                acc[i][j] += __shfl_xor_sync(0xffffffffu, acc[i][j], m);
#pragma unroll
        for (int i = 0; i < 4; i++) {
            nxa[i] += __shfl_xor_sync(0xffffffffu, nxa[i], m);
            nya[i] += __shfl_xor_sync(0xffffffffu, nya[i], m);
        }
    }

    if (kp == 0) {
#pragma unroll
        for (int i = 0; i < 4; i++)
#pragma unroll
            for (int j = 0; j < 4; j++)
                g_scr[s][bh][(c0 + i) * 16 + (d0 + j)] = acc[i][j];
        if (dg == 0) {
#pragma unroll
            for (int i = 0; i < 4; i++) g_scr[s][bh][256 + c0 + i] = nxa[i];
        }
        if (w == 0) {
#pragma unroll
            for (int j = 0; j < 4; j++) g_scr[s][bh][272 + d0 + j] = nya[j];
        }
    }
}

// ---------------------------------------------------------------------------
// Kernel 2: energy, dual softmax, temperature pre-scale
// ---------------------------------------------------------------------------
__global__ __launch_bounds__(256) void k_attn(const float* __restrict__ t1p,
                                              const float* __restrict__ t2p) {
    const int bh = blockIdx.x;
    const int t  = threadIdx.x;
    __shared__ float sE[256];
    __shared__ float sNx[16];
    __shared__ float sNy[16];

    float gsum = 0.f;
#pragma unroll
    for (int s = 0; s < SPLITS; s++) gsum += g_scr[s][bh][t];
    if (t < 16) {
        float nx = 0.f;
#pragma unroll
        for (int s = 0; s < SPLITS; s++) nx += g_scr[s][bh][256 + t];
        sNx[t] = fmaxf(sqrtf(nx), 1e-12f);
    } else if (t < 32) {
        const int d = t - 16;
        float ny = 0.f;
#pragma unroll
        for (int s = 0; s < SPLITS; s++) ny += g_scr[s][bh][272 + d];
        sNy[d] = fmaxf(sqrtf(ny), 1e-12f);
    }
    __syncthreads();

    const int c = t >> 4, d = t & 15;
    const float e = gsum / (sNx[c] * sNy[d]);
    sE[t] = e;

    // attn1: softmax over d (lane low 4 bits)
    float m = e;
#pragma unroll
    for (int msk = 1; msk <= 8; msk <<= 1)
        m = fmaxf(m, __shfl_xor_sync(0xffffffffu, m, msk));
    float p = __expf(e - m);
    float Z = p;
#pragma unroll
    for (int msk = 1; msk <= 8; msk <<= 1)
        Z += __shfl_xor_sync(0xffffffffu, Z, msk);
    g_M1[bh][t] = t1p[0] * (p / Z);

    __syncthreads();
    // attn2[c][d] = softmax over column of energy
    const float f = sE[d * 16 + c];
    float m2 = f;
#pragma unroll
    for (int msk = 1; msk <= 8; msk <<= 1)
        m2 = fmaxf(m2, __shfl_xor_sync(0xffffffffu, m2, msk));
    float p2 = __expf(f - m2);
    float Z2 = p2;
#pragma unroll
    for (int msk = 1; msk <= 8; msk <<= 1)
        Z2 += __shfl_xor_sync(0xffffffffu, Z2, msk);
    g_M2[bh][t] = t2p[0] * (p2 / Z2);
}

// ---------------------------------------------------------------------------
// Kernel 3: apply attention + residual + concat.
// bh traversed in DESCENDING order: k_gram finished reading high-bh data last,
// so those lines are still L2-resident -> apply's reads hit L2 instead of HBM.
// Duplicate-packed u64 matrices in smem; fma.rn.f32x2; streaming hints.
// out[:, 0:64]  = t2 * x_att + y
// out[:, 64:128]= t1 * y_att + x
// ---------------------------------------------------------------------------
__global__ __launch_bounds__(128) void k_apply(const float* __restrict__ x,
                                               const float* __restrict__ y,
                                               float* __restrict__ out) {
    const int bh = NBH - 1 - (int)blockIdx.y;    // reversed: chase L2 residue
    const int kc = blockIdx.x;
    const int t  = threadIdx.x;
    __shared__ u64 sD1[256];   // pk2(m1, m1)
    __shared__ u64 sD2[256];   // pk2(m2, m2)
    {
        float a0 = g_M1[bh][t],       b0 = g_M2[bh][t];
        float a1 = g_M1[bh][t + 128], b1 = g_M2[bh][t + 128];
        sD1[t]       = pk2(a0, a0);
        sD2[t]       = pk2(b0, b0);
        sD1[t + 128] = pk2(a1, a1);
        sD2[t + 128] = pk2(b1, b1);
    }
    __syncthreads();

    const int b = bh >> 2, h = bh & 3;
    const int k4 = kc * 128 + t;                 // 16-byte column index
    const char* xb = reinterpret_cast<const char*>(x + (size_t)bh * CPH * HW);
    const char* yb = reinterpret_cast<const char*>(y + (size_t)bh * CPH * HW);

    U2 xv[16], yv[16];
#pragma unroll
    for (int c = 0; c < 16; c++) {
        xv[c] = ldcs_u2(xb + ((size_t)c * (HW / 4) + k4) * 16);
        yv[c] = ldcs_u2(yb + ((size_t)c * (HW / 4) + k4) * 16);
    }

    char* ob = reinterpret_cast<char*>(out + (size_t)b * 128 * HW);
#pragma unroll
    for (int d = 0; d < 16; d++) {
        U2 ay, ax;
        ay.a = xv[d].a; ay.b = xv[d].b;   // y_ = t1*y_att + x
        ax.a = yv[d].a; ax.b = yv[d].b;   // x_ = t2*x_att + y
#pragma unroll
        for (int c = 0; c < 16; c++) {
            const u64 m1d = sD1[c * 16 + d];
            const u64 m2d = sD2[c * 16 + d];
            ay.a = fma2(m1d, yv[c].a, ay.a);
            ay.b = fma2(m1d, yv[c].b, ay.b);
            ax.a = fma2(m2d, xv[c].a, ax.a);
            ax.b = fma2(m2d, xv[c].b, ax.b);
        }
        stcs_u2(ob + ((size_t)(h * 16 + d) * (HW / 4) + k4) * 16, ax);       // ch 0..63
        stcs_u2(ob + ((size_t)(64 + h * 16 + d) * (HW / 4) + k4) * 16, ay);  // ch 64..127
    }
}

// ---------------------------------------------------------------------------
extern "C" void kernel_launch(void* const* d_in, const int* in_sizes, int n_in,
                              void* d_out, int out_size) {
    const float* x  = (const float*)d_in[0];
    const float* y  = (const float*)d_in[1];
    const float* t1 = (const float*)d_in[2];
    const float* t2 = (const float*)d_in[3];
    float* out = (float*)d_out;

    k_gram<<<dim3(SPLITS, NBH), 128>>>(x, y);
    k_attn<<<NBH, 256>>>(t1, t2);
    k_apply<<<dim3(HW / 4 / 128, NBH), 128>>>(x, y, out);
}